// round 1
// baseline (speedup 1.0000x reference)
#include <cuda_runtime.h>
#include <cuda_bf16.h>

#define D 512
#define MARGIN 1.0f
#define WARPS_PER_BLOCK 8
#define THREADS_PER_BLOCK (WARPS_PER_BLOCK * 32)

__global__ void zero_out_kernel(float* out) {
    if (threadIdx.x == 0 && blockIdx.x == 0) out[0] = 0.0f;
}

__global__ void __launch_bounds__(THREADS_PER_BLOCK)
triplet_loss_kernel(const float* __restrict__ batch,
                    const int* __restrict__ triplets,
                    float* __restrict__ out,
                    int bs) {
    __shared__ float block_sum;
    if (threadIdx.x == 0) block_sum = 0.0f;
    __syncthreads();

    const int lane = threadIdx.x & 31;
    const int warp_global = (blockIdx.x * blockDim.x + threadIdx.x) >> 5;

    if (warp_global < bs) {
        // All 32 lanes load the same 3 indices (L1 broadcast, no penalty)
        const int ia = triplets[warp_global * 3 + 0];
        const int ip = triplets[warp_global * 3 + 1];
        const int in = triplets[warp_global * 3 + 2];

        const float4* __restrict__ A = reinterpret_cast<const float4*>(batch + (size_t)ia * D);
        const float4* __restrict__ P = reinterpret_cast<const float4*>(batch + (size_t)ip * D);
        const float4* __restrict__ N = reinterpret_cast<const float4*>(batch + (size_t)in * D);

        float d_ap = 0.0f;
        float d_an = 0.0f;

        // 512 floats = 128 float4; 32 lanes * 4 iterations.
        // 12 independent LDG.128 per thread -> high MLP to hide L2 latency.
        #pragma unroll
        for (int j = 0; j < 4; j++) {
            const int idx = lane + j * 32;
            const float4 a = A[idx];
            const float4 p = P[idx];
            const float4 n = N[idx];

            float dx;
            dx = a.x - p.x; d_ap = fmaf(dx, dx, d_ap);
            dx = a.y - p.y; d_ap = fmaf(dx, dx, d_ap);
            dx = a.z - p.z; d_ap = fmaf(dx, dx, d_ap);
            dx = a.w - p.w; d_ap = fmaf(dx, dx, d_ap);

            dx = a.x - n.x; d_an = fmaf(dx, dx, d_an);
            dx = a.y - n.y; d_an = fmaf(dx, dx, d_an);
            dx = a.z - n.z; d_an = fmaf(dx, dx, d_an);
            dx = a.w - n.w; d_an = fmaf(dx, dx, d_an);
        }

        // Warp tree reduction of both distances
        #pragma unroll
        for (int off = 16; off > 0; off >>= 1) {
            d_ap += __shfl_down_sync(0xFFFFFFFFu, d_ap, off);
            d_an += __shfl_down_sync(0xFFFFFFFFu, d_an, off);
        }

        if (lane == 0) {
            const float loss = d_ap - d_an + MARGIN;
            if (loss > 0.0f) atomicAdd(&block_sum, loss);
        }
    }

    __syncthreads();
    if (threadIdx.x == 0) {
        const float s = block_sum;
        if (s != 0.0f) atomicAdd(out, s);
    }
}

extern "C" void kernel_launch(void* const* d_in, const int* in_sizes, int n_in,
                              void* d_out, int out_size) {
    const float* batch    = (const float*)d_in[0];
    const int*   triplets = (const int*)d_in[1];
    float* out = (float*)d_out;

    const int bs = in_sizes[1] / 3;  // 16384 triplets

    zero_out_kernel<<<1, 32>>>(out);

    const int blocks = (bs + WARPS_PER_BLOCK - 1) / WARPS_PER_BLOCK;
    triplet_loss_kernel<<<blocks, THREADS_PER_BLOCK>>>(batch, triplets, out, bs);
}